// round 9
// baseline (speedup 1.0000x reference)
#include <cuda_runtime.h>

// Problem constants (fixed: B=65536, T=100, D_CP=2, D_FIN=3, HID=12, D_OUT=2)
#define BT_B 65536
#define BT_T 100

#define ROWS_PER_CTA 64
#define WIN 20                       // timesteps per staged window (5 windows)
#define WFLO (WIN * 3)               // 60 floats per row per window
#define SSTR 61                      // SMEM row stride: odd => conflict-free LDS

typedef unsigned long long u64;

__device__ __forceinline__ u64 pack2(float lo, float hi) {
    u64 r; asm("mov.b64 %0, {%1, %2};" : "=l"(r) : "f"(lo), "f"(hi)); return r;
}
__device__ __forceinline__ void unpack2(u64 v, float& lo, float& hi) {
    asm("mov.b64 {%0, %1}, %2;" : "=f"(lo), "=f"(hi) : "l"(v));
}
__device__ __forceinline__ u64 fma2(u64 a, u64 b, u64 c) {
    u64 d; asm("fma.rn.f32x2 %0, %1, %2, %3;" : "=l"(d) : "l"(a), "l"(b), "l"(c)); return d;
}
__device__ __forceinline__ u64 mul2(u64 a, u64 b) {
    u64 d; asm("mul.rn.f32x2 %0, %1, %2;" : "=l"(d) : "l"(a), "l"(b)); return d;
}
__device__ __forceinline__ float tanhapx(float x) {
    float r; asm("tanh.approx.f32 %0, %1;" : "=f"(r) : "f"(x)); return r;
}

// Two threads per batch row (half ∈ {0,1} owns hidden units [6h,6h+6)).
// Finger input staged through SMEM in 20-step windows with coalesced loads,
// eliminating strided-LDG wavefront inflation from the recurrence loop.
__global__ __launch_bounds__(128, 7)
void deform_tracker_kernel(const float* __restrict__ cp,     // (B, T, 2)
                           const float* __restrict__ fin,    // (B, T, 3)
                           const float* __restrict__ Wr,     // (5, 12)
                           const float* __restrict__ br,     // (12,)
                           const float* __restrict__ Wo,     // (14, 2)
                           const float* __restrict__ bo,     // (2,)
                           float* __restrict__ out)          // (B, T, 2)
{
    __shared__ float sfin[ROWS_PER_CTA * SSTR];   // 64*61*4 = 15.6 KB

    const int tid  = threadIdx.x;
    const int lrow = tid >> 1;
    const int half = tid & 1;
    const int cbase = 6 * half;
    const int row0 = blockIdx.x * ROWS_PER_CTA;
    const int row  = row0 + lrow;

    // ---- Register-resident weights (own half of the hidden dim) ----
    u64 Wp[5][3];
    #pragma unroll
    for (int i = 0; i < 5; i++)
        #pragma unroll
        for (int k = 0; k < 3; k++)
            Wp[i][k] = pack2(__ldg(Wr + i * 12 + cbase + 2 * k),
                             __ldg(Wr + i * 12 + cbase + 2 * k + 1));

    u64 wup[3], wvp[3];
    #pragma unroll
    for (int k = 0; k < 3; k++) {
        wup[k] = pack2(__ldg(Wo + (2 + cbase + 2 * k) * 2 + 0),
                       __ldg(Wo + (3 + cbase + 2 * k) * 2 + 0));
        wvp[k] = pack2(__ldg(Wo + (2 + cbase + 2 * k) * 2 + 1),
                       __ldg(Wo + (3 + cbase + 2 * k) * 2 + 1));
    }
    const float w00 = __ldg(Wo + 0), w01 = __ldg(Wo + 1);
    const float w10 = __ldg(Wo + 2), w11 = __ldg(Wo + 3);
    const float bo0 = __ldg(bo + 0), bo1 = __ldg(bo + 1);

    // ---- Per-row invariants ----
    const float2 cp0 = *reinterpret_cast<const float2*>(cp + (size_t)row * (BT_T * 2));
    const float c0 = fmaf(cp0.x, w00, fmaf(cp0.y, w10, bo0));
    const float c1 = fmaf(cp0.x, w01, fmaf(cp0.y, w11, bo1));

    u64 base[3];
    {
        u64 p0 = pack2(c0, c0), p1 = pack2(c1, c1);
        #pragma unroll
        for (int k = 0; k < 3; k++) {
            u64 brp = pack2(__ldg(br + cbase + 2 * k), __ldg(br + cbase + 2 * k + 1));
            base[k] = fma2(p1, Wp[1][k], fma2(p0, Wp[0][k], brp));
        }
    }

    float u = cp0.x - c0, v = cp0.y - c1;

    const float* finb = fin + (size_t)row0 * (BT_T * 3);     // CTA's 64-row block
    float4* op = reinterpret_cast<float4*>(out + (size_t)row * (BT_T * 2));
    const float* myf = &sfin[lrow * SSTR];

    #pragma unroll 1
    for (int w = 0; w < BT_T / WIN; w++) {
        // ---- Stage window w: 64 rows x 60 floats, coalesced (3840 = 30*128) ----
        #pragma unroll 1
        for (int j = tid; j < ROWS_PER_CTA * WFLO; j += 128) {
            int r = j / WFLO;                 // constant divide -> IMAD sequence
            int k = j - r * WFLO;
            sfin[r * SSTR + k] = finb[(size_t)r * (BT_T * 3) + w * WFLO + k];
        }
        __syncthreads();

        // ---- Compute 20 steps (10 chunks of 2), fin via conflict-free broadcast LDS ----
        #pragma unroll 1
        for (int c = 0; c < WIN / 2; c++) {
            float f[6];
            #pragma unroll
            for (int i = 0; i < 6; i++) f[i] = myf[6 * c + i];
            float res[4];

            #pragma unroll
            for (int s = 0; s < 2; s++) {
                // Off-chain partial: base + fin_t @ Wr[2:5]
                u64 px2 = pack2(f[3 * s + 0], f[3 * s + 0]);
                u64 px3 = pack2(f[3 * s + 1], f[3 * s + 1]);
                u64 px4 = pack2(f[3 * s + 2], f[3 * s + 2]);
                u64 part[3];
                #pragma unroll
                for (int k = 0; k < 3; k++)
                    part[k] = fma2(px4, Wp[4][k], fma2(px3, Wp[3][k], fma2(px2, Wp[2][k], base[k])));

                // Critical chain: + u*Wr0 + v*Wr1, tanh
                u64 pu = pack2(u, u), pv = pack2(v, v);
                float h[6];
                #pragma unroll
                for (int k = 0; k < 3; k++) {
                    u64 a = fma2(pv, Wp[1][k], fma2(pu, Wp[0][k], part[k]));
                    float a0, a1;
                    unpack2(a, a0, a1);
                    h[2 * k + 0] = tanhapx(a0);
                    h[2 * k + 1] = tanhapx(a1);
                }

                // Packed output dot: uo = h.wu, vo = h.wv
                u64 hp0 = pack2(h[0], h[1]);
                u64 hp1 = pack2(h[2], h[3]);
                u64 hp2 = pack2(h[4], h[5]);
                u64 au = fma2(hp2, wup[2], fma2(hp1, wup[1], mul2(hp0, wup[0])));
                u64 av = fma2(hp2, wvp[2], fma2(hp1, wvp[1], mul2(hp0, wvp[0])));
                float ul, uh, vl, vh;
                unpack2(au, ul, uh);
                unpack2(av, vl, vh);
                float uo = ul + uh, vo = vl + vh;

                // Exchange partner's partial; both threads hold full (u,v)
                float up = __shfl_xor_sync(0xFFFFFFFFu, uo, 1);
                float vp = __shfl_xor_sync(0xFFFFFFFFu, vo, 1);
                u = uo + up;
                v = vo + vp;

                res[2 * s + 0] = c0 + u;
                res[2 * s + 1] = c1 + v;
            }

            // Alternate which pair-thread stores this chunk (lockstep-identical values)
            if (half == (c & 1)) {
                op[w * (WIN / 2) + c] = make_float4(res[0], res[1], res[2], res[3]);
            }
        }
        __syncthreads();   // protect sfin before next window's restage
    }
}

extern "C" void kernel_launch(void* const* d_in, const int* in_sizes, int n_in,
                              void* d_out, int out_size) {
    const float* cp  = (const float*)d_in[0];  // control_point_input (B,T,2)
    const float* fin = (const float*)d_in[1];  // finger_input (B,T,3)
    const float* Wr  = (const float*)d_in[2];  // W_rnn (5,12)
    // d_in[3] = U_rnn — mathematically inert (hidden state reset each step)
    const float* br  = (const float*)d_in[4];  // b_rnn (12,)
    const float* Wo  = (const float*)d_in[5];  // W_out (14,2)
    const float* bo  = (const float*)d_in[6];  // b_out (2,)
    float* out = (float*)d_out;

    const int blocks = BT_B / ROWS_PER_CTA;    // 1024 = one wave at 7 CTAs/SM
    deform_tracker_kernel<<<blocks, 128>>>(cp, fin, Wr, br, Wo, bo, out);
}

// round 10
// speedup vs baseline: 1.7163x; 1.7163x over previous
#include <cuda_runtime.h>

// Problem constants (fixed: B=65536, T=100, D_CP=2, D_FIN=3, HID=12, D_OUT=2)
#define BT_B 65536
#define BT_T 100

typedef unsigned long long u64;

__device__ __forceinline__ u64 pack2(float lo, float hi) {
    u64 r; asm("mov.b64 %0, {%1, %2};" : "=l"(r) : "f"(lo), "f"(hi)); return r;
}
__device__ __forceinline__ void unpack2(u64 v, float& lo, float& hi) {
    asm("mov.b64 {%0, %1}, %2;" : "=f"(lo), "=f"(hi) : "l"(v));
}
__device__ __forceinline__ u64 fma2(u64 a, u64 b, u64 c) {
    u64 d; asm("fma.rn.f32x2 %0, %1, %2, %3;" : "=l"(d) : "l"(a), "l"(b), "l"(c)); return d;
}
__device__ __forceinline__ u64 mul2(u64 a, u64 b) {
    u64 d; asm("mul.rn.f32x2 %0, %1, %2;" : "=l"(d) : "l"(a), "l"(b)); return d;
}
__device__ __forceinline__ float tanhapx(float x) {
    float r; asm("tanh.approx.f32 %0, %1;" : "=f"(r) : "f"(x)); return r;
}

// One thread per batch row. Full weights register-resident (no LDS, no shfl).
// 512 blocks @ 4 CTAs/SM = exactly one wave.
__global__ __launch_bounds__(128, 4)
void deform_tracker_kernel(const float* __restrict__ cp,     // (B, T, 2)
                           const float* __restrict__ fin,    // (B, T, 3)
                           const float* __restrict__ Wr,     // (5, 12)
                           const float* __restrict__ br,     // (12,)
                           const float* __restrict__ Wo,     // (14, 2)
                           const float* __restrict__ bo,     // (2,)
                           float* __restrict__ out)          // (B, T, 2)
{
    const int row = blockIdx.x * blockDim.x + threadIdx.x;   // 0 .. 65535

    // ---- Register-resident weights: all 12 hidden units, packed in f32x2 pairs ----
    u64 Wp[5][6];
    #pragma unroll
    for (int i = 0; i < 5; i++)
        #pragma unroll
        for (int k = 0; k < 6; k++)
            Wp[i][k] = pack2(__ldg(Wr + i * 12 + 2 * k), __ldg(Wr + i * 12 + 2 * k + 1));

    // Output weights packed over hidden pairs: wup[k] = (Wo[2+2k][0], Wo[3+2k][0])
    u64 wup[6], wvp[6];
    #pragma unroll
    for (int k = 0; k < 6; k++) {
        wup[k] = pack2(__ldg(Wo + (2 + 2 * k) * 2 + 0), __ldg(Wo + (3 + 2 * k) * 2 + 0));
        wvp[k] = pack2(__ldg(Wo + (2 + 2 * k) * 2 + 1), __ldg(Wo + (3 + 2 * k) * 2 + 1));
    }
    const float w00 = __ldg(Wo + 0), w01 = __ldg(Wo + 1);
    const float w10 = __ldg(Wo + 2), w11 = __ldg(Wo + 3);
    const float bo0 = __ldg(bo + 0), bo1 = __ldg(bo + 1);

    // ---- Per-row invariants ----
    const float2 cp0 = *reinterpret_cast<const float2*>(cp + (size_t)row * (BT_T * 2));
    const float c0 = fmaf(cp0.x, w00, fmaf(cp0.y, w10, bo0));
    const float c1 = fmaf(cp0.x, w01, fmaf(cp0.y, w11, bo1));

    // base[k] = br + c0*Wr0 + c1*Wr1 (constant part of fed-back input o = (c0+u, c1+v))
    u64 base[6];
    {
        u64 p0 = pack2(c0, c0), p1 = pack2(c1, c1);
        #pragma unroll
        for (int k = 0; k < 6; k++) {
            u64 brp = pack2(__ldg(br + 2 * k), __ldg(br + 2 * k + 1));
            base[k] = fma2(p1, Wp[1][k], fma2(p0, Wp[0][k], brp));
        }
    }

    float u = cp0.x - c0, v = cp0.y - c1;

    const float2* fp = reinterpret_cast<const float2*>(fin + (size_t)row * (BT_T * 3));
    float4* op = reinterpret_cast<float4*>(out + (size_t)row * (BT_T * 2));

    // Depth-1 prefetch of the next chunk's finger data (3 x float2 per 2 steps)
    float2 nf0 = fp[0], nf1 = fp[1], nf2 = fp[2];

    #pragma unroll 1
    for (int c = 0; c < BT_T / 2; c++) {
        const float2 g0 = nf0, g1 = nf1, g2 = nf2;
        const int pc = (c < BT_T / 2 - 1) ? (c + 1) : c;   // clamp, no OOB
        nf0 = fp[3 * pc + 0];
        nf1 = fp[3 * pc + 1];
        nf2 = fp[3 * pc + 2];

        const float f[6] = {g0.x, g0.y, g1.x, g1.y, g2.x, g2.y};
        float res[4];

        #pragma unroll
        for (int s = 0; s < 2; s++) {
            // Off-chain partial (independent of u,v): base + fin_t @ Wr[2:5]
            u64 px2 = pack2(f[3 * s + 0], f[3 * s + 0]);
            u64 px3 = pack2(f[3 * s + 1], f[3 * s + 1]);
            u64 px4 = pack2(f[3 * s + 2], f[3 * s + 2]);

            // Critical chain: + u*Wr0 + v*Wr1, tanh — all 12 hidden units
            u64 pu = pack2(u, u), pv = pack2(v, v);
            float h[12];
            #pragma unroll
            for (int k = 0; k < 6; k++) {
                u64 part = fma2(px4, Wp[4][k], fma2(px3, Wp[3][k], fma2(px2, Wp[2][k], base[k])));
                u64 a = fma2(pv, Wp[1][k], fma2(pu, Wp[0][k], part));
                float a0, a1;
                unpack2(a, a0, a1);
                h[2 * k + 0] = tanhapx(a0);
                h[2 * k + 1] = tanhapx(a1);
            }

            // Packed output dots with split accumulators: u = h.wu, v = h.wv
            u64 hp[6];
            #pragma unroll
            for (int k = 0; k < 6; k++) hp[k] = pack2(h[2 * k], h[2 * k + 1]);

            u64 ua = mul2(hp[0], wup[0]), ub = mul2(hp[1], wup[1]);
            u64 va = mul2(hp[0], wvp[0]), vb = mul2(hp[1], wvp[1]);
            #pragma unroll
            for (int k = 2; k < 6; k += 2) {
                ua = fma2(hp[k],     wup[k],     ua);
                ub = fma2(hp[k + 1], wup[k + 1], ub);
                va = fma2(hp[k],     wvp[k],     va);
                vb = fma2(hp[k + 1], wvp[k + 1], vb);
            }
            float ua0, ua1, ub0, ub1, va0, va1, vb0, vb1;
            unpack2(ua, ua0, ua1);
            unpack2(ub, ub0, ub1);
            unpack2(va, va0, va1);
            unpack2(vb, vb0, vb1);
            u = (ua0 + ua1) + (ub0 + ub1);
            v = (va0 + va1) + (vb0 + vb1);

            res[2 * s + 0] = c0 + u;
            res[2 * s + 1] = c1 + v;
        }

        op[c] = make_float4(res[0], res[1], res[2], res[3]);
    }
}

extern "C" void kernel_launch(void* const* d_in, const int* in_sizes, int n_in,
                              void* d_out, int out_size) {
    const float* cp  = (const float*)d_in[0];  // control_point_input (B,T,2)
    const float* fin = (const float*)d_in[1];  // finger_input (B,T,3)
    const float* Wr  = (const float*)d_in[2];  // W_rnn (5,12)
    // d_in[3] = U_rnn — mathematically inert (hidden state reset each step)
    const float* br  = (const float*)d_in[4];  // b_rnn (12,)
    const float* Wo  = (const float*)d_in[5];  // W_out (14,2)
    const float* bo  = (const float*)d_in[6];  // b_out (2,)
    float* out = (float*)d_out;

    const int threads = 128;
    const int blocks = BT_B / threads;          // 512 = one wave at 4 CTAs/SM
    deform_tracker_kernel<<<blocks, threads>>>(cp, fin, Wr, br, Wo, bo, out);
}

// round 11
// speedup vs baseline: 1.7288x; 1.0073x over previous
#include <cuda_runtime.h>

// Problem constants (fixed: B=65536, T=100, D_CP=2, D_FIN=3, HID=12, D_OUT=2)
#define BT_B 65536
#define BT_T 100

#define ROWS_PER_CTA 64
#define WIN 20                   // timesteps per window (5 windows)
#define SSTR 60                  // SMEM row stride in floats (16B-aligned rows)

typedef unsigned long long u64;

__device__ __forceinline__ u64 pack2(float lo, float hi) {
    u64 r; asm("mov.b64 %0, {%1, %2};" : "=l"(r) : "f"(lo), "f"(hi)); return r;
}
__device__ __forceinline__ void unpack2(u64 v, float& lo, float& hi) {
    asm("mov.b64 {%0, %1}, %2;" : "=f"(lo), "=f"(hi) : "l"(v));
}
__device__ __forceinline__ u64 fma2(u64 a, u64 b, u64 c) {
    u64 d; asm("fma.rn.f32x2 %0, %1, %2, %3;" : "=l"(d) : "l"(a), "l"(b), "l"(c)); return d;
}
__device__ __forceinline__ u64 mul2(u64 a, u64 b) {
    u64 d; asm("mul.rn.f32x2 %0, %1, %2;" : "=l"(d) : "l"(a), "l"(b)); return d;
}
__device__ __forceinline__ float tanhapx(float x) {
    float r; asm("tanh.approx.f32 %0, %1;" : "=f"(r) : "f"(x)); return r;
}
__device__ __forceinline__ void cpasync16(unsigned dst, const void* src) {
    asm volatile("cp.async.ca.shared.global [%0], [%1], 16;" :: "r"(dst), "l"(src) : "memory");
}
__device__ __forceinline__ void cpasync_commit() {
    asm volatile("cp.async.commit_group;" ::: "memory");
}
__device__ __forceinline__ void cpasync_wait0() {
    asm volatile("cp.async.wait_group 0;" ::: "memory");
}

// Two threads per batch row (half ∈ {0,1} owns hidden units [6h,6h+6)).
// Finger input staged via cp.async double-buffered SMEM windows (coalesced,
// register-free) to kill the L1tex wavefront-queue bottleneck of strided LDG.
__global__ __launch_bounds__(128, 7)
void deform_tracker_kernel(const float* __restrict__ cp,     // (B, T, 2)
                           const float* __restrict__ fin,    // (B, T, 3)
                           const float* __restrict__ Wr,     // (5, 12)
                           const float* __restrict__ br,     // (12,)
                           const float* __restrict__ Wo,     // (14, 2)
                           const float* __restrict__ bo,     // (2,)
                           float* __restrict__ out)          // (B, T, 2)
{
    __shared__ float sfin[2][ROWS_PER_CTA * SSTR];   // 2 x 15.36 KB

    const int tid  = threadIdx.x;
    const int lrow = tid >> 1;
    const int half = tid & 1;
    const int cbase = 6 * half;
    const int row0 = blockIdx.x * ROWS_PER_CTA;
    const int row  = row0 + lrow;

    // SMEM base address (for cp.async)
    unsigned sbase;
    asm("{ .reg .u64 t; cvta.to.shared.u64 t, %1; cvt.u32.u64 %0, t; }"
        : "=r"(sbase) : "l"(&sfin[0][0]));

    // ---- Register-resident weights (own half of the hidden dim) ----
    u64 Wp[5][3];
    #pragma unroll
    for (int i = 0; i < 5; i++)
        #pragma unroll
        for (int k = 0; k < 3; k++)
            Wp[i][k] = pack2(__ldg(Wr + i * 12 + cbase + 2 * k),
                             __ldg(Wr + i * 12 + cbase + 2 * k + 1));

    u64 wup[3], wvp[3];
    #pragma unroll
    for (int k = 0; k < 3; k++) {
        wup[k] = pack2(__ldg(Wo + (2 + cbase + 2 * k) * 2 + 0),
                       __ldg(Wo + (3 + cbase + 2 * k) * 2 + 0));
        wvp[k] = pack2(__ldg(Wo + (2 + cbase + 2 * k) * 2 + 1),
                       __ldg(Wo + (3 + cbase + 2 * k) * 2 + 1));
    }
    const float w00 = __ldg(Wo + 0), w01 = __ldg(Wo + 1);
    const float w10 = __ldg(Wo + 2), w11 = __ldg(Wo + 3);
    const float bo0 = __ldg(bo + 0), bo1 = __ldg(bo + 1);

    // ---- Per-row invariants ----
    const float2 cp0 = *reinterpret_cast<const float2*>(cp + (size_t)row * (BT_T * 2));
    const float c0 = fmaf(cp0.x, w00, fmaf(cp0.y, w10, bo0));
    const float c1 = fmaf(cp0.x, w01, fmaf(cp0.y, w11, bo1));

    u64 base[3];
    {
        u64 p0 = pack2(c0, c0), p1 = pack2(c1, c1);
        #pragma unroll
        for (int k = 0; k < 3; k++) {
            u64 brp = pack2(__ldg(br + cbase + 2 * k), __ldg(br + cbase + 2 * k + 1));
            base[k] = fma2(p1, Wp[1][k], fma2(p0, Wp[0][k], brp));
        }
    }

    float u = cp0.x - c0, v = cp0.y - c1;

    // fin as float4: row stride 75, window offset 15 per window
    const float4* fin4 = reinterpret_cast<const float4*>(fin) + (size_t)row0 * 75;
    float4* op = reinterpret_cast<float4*>(out + (size_t)row * (BT_T * 2));

    // ---- Stage one window: 64 rows x 15 float4, coalesced cp.async, full MLP ----
    auto stage = [&](int w, int buf) {
        const float4* src = fin4 + (size_t)w * 15;
        unsigned db = sbase + (unsigned)buf * (ROWS_PER_CTA * SSTR * 4);
        #pragma unroll
        for (int i = 0; i < 8; i++) {
            int j = tid + i * 128;                 // 0..1023, need j < 960
            if (i < 7 || j < 960) {
                int r = j / 15, ch = j - r * 15;   // chunk-fastest: coalesced per row
                cpasync16(db + (unsigned)(r * SSTR + ch * 4) * 4,
                          src + (size_t)r * 75 + ch);
            }
        }
        cpasync_commit();
    };

    stage(0, 0);
    cpasync_wait0();
    __syncthreads();

    #pragma unroll 1
    for (int w = 0; w < BT_T / WIN; w++) {
        if (w < BT_T / WIN - 1) stage(w + 1, (w + 1) & 1);   // async, overlaps compute

        const float* myf = &sfin[w & 1][lrow * SSTR];

        // ---- Compute WIN steps (10 chunks of 2) ----
        #pragma unroll 1
        for (int c = 0; c < WIN / 2; c++) {
            float2 g0 = *reinterpret_cast<const float2*>(myf + 6 * c + 0);
            float2 g1 = *reinterpret_cast<const float2*>(myf + 6 * c + 2);
            float2 g2 = *reinterpret_cast<const float2*>(myf + 6 * c + 4);
            const float f[6] = {g0.x, g0.y, g1.x, g1.y, g2.x, g2.y};
            float res[4];

            #pragma unroll
            for (int s = 0; s < 2; s++) {
                // Off-chain partial: base + fin_t @ Wr[2:5]
                u64 px2 = pack2(f[3 * s + 0], f[3 * s + 0]);
                u64 px3 = pack2(f[3 * s + 1], f[3 * s + 1]);
                u64 px4 = pack2(f[3 * s + 2], f[3 * s + 2]);
                u64 part[3];
                #pragma unroll
                for (int k = 0; k < 3; k++)
                    part[k] = fma2(px4, Wp[4][k], fma2(px3, Wp[3][k], fma2(px2, Wp[2][k], base[k])));

                // Critical chain: + u*Wr0 + v*Wr1, tanh
                u64 pu = pack2(u, u), pv = pack2(v, v);
                float h[6];
                #pragma unroll
                for (int k = 0; k < 3; k++) {
                    u64 a = fma2(pv, Wp[1][k], fma2(pu, Wp[0][k], part[k]));
                    float a0, a1;
                    unpack2(a, a0, a1);
                    h[2 * k + 0] = tanhapx(a0);
                    h[2 * k + 1] = tanhapx(a1);
                }

                // Packed output dot: uo = h.wu, vo = h.wv
                u64 hp0 = pack2(h[0], h[1]);
                u64 hp1 = pack2(h[2], h[3]);
                u64 hp2 = pack2(h[4], h[5]);
                u64 au = fma2(hp2, wup[2], fma2(hp1, wup[1], mul2(hp0, wup[0])));
                u64 av = fma2(hp2, wvp[2], fma2(hp1, wvp[1], mul2(hp0, wvp[0])));
                float ul, uh, vl, vh;
                unpack2(au, ul, uh);
                unpack2(av, vl, vh);
                float uo = ul + uh, vo = vl + vh;

                // Exchange partner's partial; both threads hold full (u,v)
                float up = __shfl_xor_sync(0xFFFFFFFFu, uo, 1);
                float vp = __shfl_xor_sync(0xFFFFFFFFu, vo, 1);
                u = uo + up;
                v = vo + vp;

                res[2 * s + 0] = c0 + u;
                res[2 * s + 1] = c1 + v;
            }

            // Alternate which pair-thread stores (lockstep-identical values)
            if (half == (c & 1)) {
                op[w * (WIN / 2) + c] = make_float4(res[0], res[1], res[2], res[3]);
            }
        }

        if (w < BT_T / WIN - 1) cpasync_wait0();   // next buffer landed
        __syncthreads();                            // all readers done + buffer visible
    }
}

extern "C" void kernel_launch(void* const* d_in, const int* in_sizes, int n_in,
                              void* d_out, int out_size) {
    const float* cp  = (const float*)d_in[0];  // control_point_input (B,T,2)
    const float* fin = (const float*)d_in[1];  // finger_input (B,T,3)
    const float* Wr  = (const float*)d_in[2];  // W_rnn (5,12)
    // d_in[3] = U_rnn — mathematically inert (hidden state reset each step)
    const float* br  = (const float*)d_in[4];  // b_rnn (12,)
    const float* Wo  = (const float*)d_in[5];  // W_out (14,2)
    const float* bo  = (const float*)d_in[6];  // b_out (2,)
    float* out = (float*)d_out;

    const int blocks = BT_B / ROWS_PER_CTA;    // 1024 = one wave at 7 CTAs/SM
    deform_tracker_kernel<<<blocks, 128>>>(cp, fin, Wr, br, Wo, bo, out);
}

// round 12
// speedup vs baseline: 1.7342x; 1.0031x over previous
#include <cuda_runtime.h>

// Problem constants (fixed: B=65536, T=100, D_CP=2, D_FIN=3, HID=12, D_OUT=2)
#define BT_B 65536
#define BT_T 100

#define ROWS_PER_CTA 64
#define WIN 20                   // timesteps per window (5 windows)
#define SSTR 60                  // SMEM row stride in floats (16B-aligned rows)

typedef unsigned long long u64;

__device__ __forceinline__ u64 pack2(float lo, float hi) {
    u64 r; asm("mov.b64 %0, {%1, %2};" : "=l"(r) : "f"(lo), "f"(hi)); return r;
}
__device__ __forceinline__ void unpack2(u64 v, float& lo, float& hi) {
    asm("mov.b64 {%0, %1}, %2;" : "=f"(lo), "=f"(hi) : "l"(v));
}
__device__ __forceinline__ u64 fma2(u64 a, u64 b, u64 c) {
    u64 d; asm("fma.rn.f32x2 %0, %1, %2, %3;" : "=l"(d) : "l"(a), "l"(b), "l"(c)); return d;
}
__device__ __forceinline__ u64 mul2(u64 a, u64 b) {
    u64 d; asm("mul.rn.f32x2 %0, %1, %2;" : "=l"(d) : "l"(a), "l"(b)); return d;
}
__device__ __forceinline__ float tanhapx(float x) {
    float r; asm("tanh.approx.f32 %0, %1;" : "=f"(r) : "f"(x)); return r;
}
__device__ __forceinline__ void cpasync16(unsigned dst, const void* src) {
    asm volatile("cp.async.ca.shared.global [%0], [%1], 16;" :: "r"(dst), "l"(src) : "memory");
}
__device__ __forceinline__ void cpasync_commit() {
    asm volatile("cp.async.commit_group;" ::: "memory");
}
__device__ __forceinline__ void cpasync_wait0() {
    asm volatile("cp.async.wait_group 0;" ::: "memory");
}

// Two threads per batch row (half ∈ {0,1} owns hidden units [6h,6h+6)).
// Finger input staged via cp.async double-buffered SMEM windows (coalesced,
// register-free) to kill the L1tex wavefront-queue bottleneck of strided LDG.
__global__ __launch_bounds__(128, 7)
void deform_tracker_kernel(const float* __restrict__ cp,     // (B, T, 2)
                           const float* __restrict__ fin,    // (B, T, 3)
                           const float* __restrict__ Wr,     // (5, 12)
                           const float* __restrict__ br,     // (12,)
                           const float* __restrict__ Wo,     // (14, 2)
                           const float* __restrict__ bo,     // (2,)
                           float* __restrict__ out)          // (B, T, 2)
{
    __shared__ float sfin[2][ROWS_PER_CTA * SSTR];   // 2 x 15.36 KB

    const int tid  = threadIdx.x;
    const int lrow = tid >> 1;
    const int half = tid & 1;
    const int cbase = 6 * half;
    const int row0 = blockIdx.x * ROWS_PER_CTA;
    const int row  = row0 + lrow;

    // SMEM base address (for cp.async)
    unsigned sbase;
    asm("{ .reg .u64 t; cvta.to.shared.u64 t, %1; cvt.u32.u64 %0, t; }"
        : "=r"(sbase) : "l"(&sfin[0][0]));

    // ---- Register-resident weights (own half of the hidden dim) ----
    u64 Wp[5][3];
    #pragma unroll
    for (int i = 0; i < 5; i++)
        #pragma unroll
        for (int k = 0; k < 3; k++)
            Wp[i][k] = pack2(__ldg(Wr + i * 12 + cbase + 2 * k),
                             __ldg(Wr + i * 12 + cbase + 2 * k + 1));

    u64 wup[3], wvp[3];
    #pragma unroll
    for (int k = 0; k < 3; k++) {
        wup[k] = pack2(__ldg(Wo + (2 + cbase + 2 * k) * 2 + 0),
                       __ldg(Wo + (3 + cbase + 2 * k) * 2 + 0));
        wvp[k] = pack2(__ldg(Wo + (2 + cbase + 2 * k) * 2 + 1),
                       __ldg(Wo + (3 + cbase + 2 * k) * 2 + 1));
    }
    const float w00 = __ldg(Wo + 0), w01 = __ldg(Wo + 1);
    const float w10 = __ldg(Wo + 2), w11 = __ldg(Wo + 3);
    const float bo0 = __ldg(bo + 0), bo1 = __ldg(bo + 1);

    // ---- Per-row invariants ----
    const float2 cp0 = *reinterpret_cast<const float2*>(cp + (size_t)row * (BT_T * 2));
    const float c0 = fmaf(cp0.x, w00, fmaf(cp0.y, w10, bo0));
    const float c1 = fmaf(cp0.x, w01, fmaf(cp0.y, w11, bo1));

    u64 base[3];
    {
        u64 p0 = pack2(c0, c0), p1 = pack2(c1, c1);
        #pragma unroll
        for (int k = 0; k < 3; k++) {
            u64 brp = pack2(__ldg(br + cbase + 2 * k), __ldg(br + cbase + 2 * k + 1));
            base[k] = fma2(p1, Wp[1][k], fma2(p0, Wp[0][k], brp));
        }
    }

    float u = cp0.x - c0, v = cp0.y - c1;

    // fin as float4: row stride 75, window offset 15 per window
    const float4* fin4 = reinterpret_cast<const float4*>(fin) + (size_t)row0 * 75;
    float4* op = reinterpret_cast<float4*>(out + (size_t)row * (BT_T * 2));

    // ---- Stage one window: 64 rows x 15 float4, coalesced cp.async, full MLP ----
    auto stage = [&](int w, int buf) {
        const float4* src = fin4 + (size_t)w * 15;
        unsigned db = sbase + (unsigned)buf * (ROWS_PER_CTA * SSTR * 4);
        #pragma unroll
        for (int i = 0; i < 8; i++) {
            int j = tid + i * 128;                 // 0..1023, need j < 960
            if (i < 7 || j < 960) {
                int r = j / 15, ch = j - r * 15;   // chunk-fastest: coalesced per row
                cpasync16(db + (unsigned)(r * SSTR + ch * 4) * 4,
                          src + (size_t)r * 75 + ch);
            }
        }
        cpasync_commit();
    };

    stage(0, 0);
    cpasync_wait0();
    __syncthreads();

    #pragma unroll 1
    for (int w = 0; w < BT_T / WIN; w++) {
        if (w < BT_T / WIN - 1) stage(w + 1, (w + 1) & 1);   // async, overlaps compute

        const float* myf = &sfin[w & 1][lrow * SSTR];

        // ---- Compute WIN steps (10 chunks of 2) ----
        #pragma unroll 1
        for (int c = 0; c < WIN / 2; c++) {
            float2 g0 = *reinterpret_cast<const float2*>(myf + 6 * c + 0);
            float2 g1 = *reinterpret_cast<const float2*>(myf + 6 * c + 2);
            float2 g2 = *reinterpret_cast<const float2*>(myf + 6 * c + 4);
            const float f[6] = {g0.x, g0.y, g1.x, g1.y, g2.x, g2.y};
            float res[4];

            #pragma unroll
            for (int s = 0; s < 2; s++) {
                // Off-chain partial: base + fin_t @ Wr[2:5]
                u64 px2 = pack2(f[3 * s + 0], f[3 * s + 0]);
                u64 px3 = pack2(f[3 * s + 1], f[3 * s + 1]);
                u64 px4 = pack2(f[3 * s + 2], f[3 * s + 2]);
                u64 part[3];
                #pragma unroll
                for (int k = 0; k < 3; k++)
                    part[k] = fma2(px4, Wp[4][k], fma2(px3, Wp[3][k], fma2(px2, Wp[2][k], base[k])));

                // Critical chain: + u*Wr0 + v*Wr1, tanh
                u64 pu = pack2(u, u), pv = pack2(v, v);
                float h[6];
                #pragma unroll
                for (int k = 0; k < 3; k++) {
                    u64 a = fma2(pv, Wp[1][k], fma2(pu, Wp[0][k], part[k]));
                    float a0, a1;
                    unpack2(a, a0, a1);
                    h[2 * k + 0] = tanhapx(a0);
                    h[2 * k + 1] = tanhapx(a1);
                }

                // Packed output dot: uo = h.wu, vo = h.wv
                u64 hp0 = pack2(h[0], h[1]);
                u64 hp1 = pack2(h[2], h[3]);
                u64 hp2 = pack2(h[4], h[5]);
                u64 au = fma2(hp2, wup[2], fma2(hp1, wup[1], mul2(hp0, wup[0])));
                u64 av = fma2(hp2, wvp[2], fma2(hp1, wvp[1], mul2(hp0, wvp[0])));
                float ul, uh, vl, vh;
                unpack2(au, ul, uh);
                unpack2(av, vl, vh);
                float uo = ul + uh, vo = vl + vh;

                // Exchange partner's partial; both threads hold full (u,v)
                float up = __shfl_xor_sync(0xFFFFFFFFu, uo, 1);
                float vp = __shfl_xor_sync(0xFFFFFFFFu, vo, 1);
                u = uo + up;
                v = vo + vp;

                res[2 * s + 0] = c0 + u;
                res[2 * s + 1] = c1 + v;
            }

            // Alternate which pair-thread stores (lockstep-identical values)
            if (half == (c & 1)) {
                op[w * (WIN / 2) + c] = make_float4(res[0], res[1], res[2], res[3]);
            }
        }

        if (w < BT_T / WIN - 1) cpasync_wait0();   // next buffer landed
        __syncthreads();                            // all readers done + buffer visible
    }
}

extern "C" void kernel_launch(void* const* d_in, const int* in_sizes, int n_in,
                              void* d_out, int out_size) {
    const float* cp  = (const float*)d_in[0];  // control_point_input (B,T,2)
    const float* fin = (const float*)d_in[1];  // finger_input (B,T,3)
    const float* Wr  = (const float*)d_in[2];  // W_rnn (5,12)
    // d_in[3] = U_rnn — mathematically inert (hidden state reset each step)
    const float* br  = (const float*)d_in[4];  // b_rnn (12,)
    const float* Wo  = (const float*)d_in[5];  // W_out (14,2)
    const float* bo  = (const float*)d_in[6];  // b_out (2,)
    float* out = (float*)d_out;

    const int blocks = BT_B / ROWS_PER_CTA;    // 1024 = one wave at 7 CTAs/SM
    deform_tracker_kernel<<<blocks, 128>>>(cp, fin, Wr, br, Wo, bo, out);
}